// round 5
// baseline (speedup 1.0000x reference)
#include <cuda_runtime.h>
#include <cstdint>

#define IN_CH   512
#define HID     16
#define OUT_CH  2
#define MAX_NODES 100000

// Scratch (device globals; no allocation allowed)
__device__ __align__(16) float g_s[MAX_NODES * 2];   // y = x@W12, then s = y*dinv
__device__ __align__(16) int   g_deg[MAX_NODES];     // zero-init; re-zeroed in phase D
__device__ __align__(16) float g_dinv[MAX_NODES];    // 1/sqrt(deg+1)
__device__ float g_c[2];                             // b1@W2 + b2
__device__ unsigned g_bar = 0;                       // grid barrier counter (reset at end)

// ---------------------------------------------------------------------------
__device__ __forceinline__ void grid_barrier(unsigned target) {
    __syncthreads();
    if (threadIdx.x == 0) {
        __threadfence();
        atomicAdd(&g_bar, 1u);
        while (*(volatile unsigned*)&g_bar < target) __nanosleep(32);
        __threadfence();
    }
    __syncthreads();
}

// ---------------------------------------------------------------------------
// One persistent kernel; all blocks resident (2/SM). 4 phases, 3 barriers.
__global__ void __launch_bounds__(256, 2)
gcn_kernel(const float* __restrict__ x,
           const int* __restrict__ row,
           const int* __restrict__ col,
           const float* __restrict__ W1,
           const float* __restrict__ b1,
           const float* __restrict__ W2,
           const float* __restrict__ b2,
           float* __restrict__ out,
           int n_edges, int n_nodes, int deg_blocks) {
    const unsigned G = gridDim.x;
    const int tid = threadIdx.x;
    __shared__ float sw0[IN_CH];
    __shared__ float sw1[IN_CH];

    // ======================= Phase A: deg || GEMM =========================
    if ((int)blockIdx.x < deg_blocks) {
        // ---- degree atomics over edges ----
        int n4 = n_edges >> 2;
        int stride = deg_blocks * blockDim.x;
        for (int t = blockIdx.x * blockDim.x + tid; t < n4; t += stride) {
            int4 c = __ldg(reinterpret_cast<const int4*>(col) + t);
            atomicAdd(&g_deg[c.x], 1);
            atomicAdd(&g_deg[c.y], 1);
            atomicAdd(&g_deg[c.z], 1);
            atomicAdd(&g_deg[c.w], 1);
        }
        if (blockIdx.x == 0 && tid < (n_edges & 3))
            atomicAdd(&g_deg[col[(n4 << 2) + tid]], 1);
    } else {
        // ---- fold W12 = W1@W2 into smem (per block; replaces prep kernel) ----
        for (int ch = tid; ch < IN_CH; ch += blockDim.x) {
            float s0 = 0.f, s1 = 0.f;
#pragma unroll
            for (int h = 0; h < HID; h++) {
                float w = __ldg(&W1[ch * HID + h]);
                s0 += w * __ldg(&W2[h * OUT_CH + 0]);
                s1 += w * __ldg(&W2[h * OUT_CH + 1]);
            }
            sw0[ch] = s0;
            sw1[ch] = s1;
        }
        __syncthreads();

        const int lane    = tid & 31;
        const int wlocal  = (((int)blockIdx.x - deg_blocks) * (int)blockDim.x + tid) >> 5;
        const int n_warps = ((int)G - deg_blocks) * ((int)blockDim.x >> 5);

        float4 wa[4], wb[4];
#pragma unroll
        for (int j = 0; j < 4; j++) {
            int idx = lane + 32 * j;
            wa[j] = reinterpret_cast<const float4*>(sw0)[idx];
            wb[j] = reinterpret_cast<const float4*>(sw1)[idx];
        }

        const float4* x4 = reinterpret_cast<const float4*>(x);
        const int n_groups = n_nodes >> 2;           // groups of 4 rows

        for (int g = wlocal; g < n_groups; g += n_warps) {
            const int rbase = g * 4;
            float4 v[4][4];
#pragma unroll
            for (int r = 0; r < 4; r++) {
                const float4* xr = x4 + (size_t)(rbase + r) * (IN_CH / 4);
#pragma unroll
                for (int j = 0; j < 4; j++) v[r][j] = __ldg(xr + lane + 32 * j);
            }
            float s00 = 0.f, s01 = 0.f, s10 = 0.f, s11 = 0.f;
            float s20 = 0.f, s21 = 0.f, s30 = 0.f, s31 = 0.f;
#pragma unroll
            for (int j = 0; j < 4; j++) {
                s00 += v[0][j].x * wa[j].x + v[0][j].y * wa[j].y + v[0][j].z * wa[j].z + v[0][j].w * wa[j].w;
                s01 += v[0][j].x * wb[j].x + v[0][j].y * wb[j].y + v[0][j].z * wb[j].z + v[0][j].w * wb[j].w;
                s10 += v[1][j].x * wa[j].x + v[1][j].y * wa[j].y + v[1][j].z * wa[j].z + v[1][j].w * wa[j].w;
                s11 += v[1][j].x * wb[j].x + v[1][j].y * wb[j].y + v[1][j].z * wb[j].z + v[1][j].w * wb[j].w;
                s20 += v[2][j].x * wa[j].x + v[2][j].y * wa[j].y + v[2][j].z * wa[j].z + v[2][j].w * wa[j].w;
                s21 += v[2][j].x * wb[j].x + v[2][j].y * wb[j].y + v[2][j].z * wb[j].z + v[2][j].w * wb[j].w;
                s30 += v[3][j].x * wa[j].x + v[3][j].y * wa[j].y + v[3][j].z * wa[j].z + v[3][j].w * wa[j].w;
                s31 += v[3][j].x * wb[j].x + v[3][j].y * wb[j].y + v[3][j].z * wb[j].z + v[3][j].w * wb[j].w;
            }
#pragma unroll
            for (int off = 16; off > 0; off >>= 1) {
                s00 += __shfl_xor_sync(0xFFFFFFFFu, s00, off);
                s01 += __shfl_xor_sync(0xFFFFFFFFu, s01, off);
                s10 += __shfl_xor_sync(0xFFFFFFFFu, s10, off);
                s11 += __shfl_xor_sync(0xFFFFFFFFu, s11, off);
                s20 += __shfl_xor_sync(0xFFFFFFFFu, s20, off);
                s21 += __shfl_xor_sync(0xFFFFFFFFu, s21, off);
                s30 += __shfl_xor_sync(0xFFFFFFFFu, s30, off);
                s31 += __shfl_xor_sync(0xFFFFFFFFu, s31, off);
            }
            if (lane < 4) {
                float o0, o1;
                if      (lane == 0) { o0 = s00; o1 = s01; }
                else if (lane == 1) { o0 = s10; o1 = s11; }
                else if (lane == 2) { o0 = s20; o1 = s21; }
                else                { o0 = s30; o1 = s31; }
                reinterpret_cast<float2*>(g_s)[rbase + lane] = make_float2(o0, o1);
            }
        }
        // scalar tail rows (none for n_nodes % 4 == 0)
        for (int r = (n_groups << 2) + wlocal; r < n_nodes; r += n_warps) {
            const float4* xr = x4 + (size_t)r * (IN_CH / 4);
            float s0 = 0.f, s1 = 0.f;
#pragma unroll
            for (int j = 0; j < 4; j++) {
                float4 v0 = __ldg(xr + lane + 32 * j);
                s0 += v0.x * wa[j].x + v0.y * wa[j].y + v0.z * wa[j].z + v0.w * wa[j].w;
                s1 += v0.x * wb[j].x + v0.y * wb[j].y + v0.z * wb[j].z + v0.w * wb[j].w;
            }
#pragma unroll
            for (int off = 16; off > 0; off >>= 1) {
                s0 += __shfl_xor_sync(0xFFFFFFFFu, s0, off);
                s1 += __shfl_xor_sync(0xFFFFFFFFu, s1, off);
            }
            if (lane == 0)
                reinterpret_cast<float2*>(g_s)[r] = make_float2(s0, s1);
        }
    }

    grid_barrier(G);

    // ============ Phase B: dinv, s = y*dinv, seed out; fold bias ==========
    if (blockIdx.x == 0 && tid == 0) {
#pragma unroll
        for (int k = 0; k < OUT_CH; k++) {
            float c = b2[k];
#pragma unroll
            for (int h = 0; h < HID; h++) c += b1[h] * W2[h * OUT_CH + k];
            g_c[k] = c;
        }
    }
    {
        int n2 = (n_nodes + 1) >> 1;
        int stride = G * blockDim.x;
        for (int t = blockIdx.x * blockDim.x + tid; t < n2; t += stride) {
            int i = t * 2;
            if (i + 1 < n_nodes) {
                float4 y = *reinterpret_cast<float4*>(g_s + i * 2);
                float d0 = rsqrtf((float)(g_deg[i] + 1));
                float d1 = rsqrtf((float)(g_deg[i + 1] + 1));
                y.x *= d0; y.y *= d0; y.z *= d1; y.w *= d1;
                *reinterpret_cast<float4*>(g_s + i * 2) = y;
                *reinterpret_cast<float4*>(out + i * 2) = y;   // seeded with s[c]
                *reinterpret_cast<float2*>(g_dinv + i) = make_float2(d0, d1);
            } else {
                float di = rsqrtf((float)(g_deg[i] + 1));
                g_dinv[i] = di;
                float2 y = reinterpret_cast<const float2*>(g_s)[i];
                float2 s = make_float2(y.x * di, y.y * di);
                reinterpret_cast<float2*>(g_s)[i] = s;
                reinterpret_cast<float2*>(out)[i] = s;
            }
        }
    }

    grid_barrier(2u * G);

    // ================= Phase C: scatter  out[c] += s[r] ===================
    {
        int n4 = n_edges >> 2;
        int stride = G * blockDim.x;
        for (int t = blockIdx.x * blockDim.x + tid; t < n4; t += stride) {
            int e = t * 4;
            int4 r = *reinterpret_cast<const int4*>(row + e);
            int4 c = *reinterpret_cast<const int4*>(col + e);
            float2 sx = __ldg(reinterpret_cast<const float2*>(g_s) + r.x);
            float2 sy = __ldg(reinterpret_cast<const float2*>(g_s) + r.y);
            float2 sz = __ldg(reinterpret_cast<const float2*>(g_s) + r.z);
            float2 sw = __ldg(reinterpret_cast<const float2*>(g_s) + r.w);
            asm volatile("red.global.add.v2.f32 [%0], {%1, %2};"
                         :: "l"(out + (size_t)c.x * 2), "f"(sx.x), "f"(sx.y) : "memory");
            asm volatile("red.global.add.v2.f32 [%0], {%1, %2};"
                         :: "l"(out + (size_t)c.y * 2), "f"(sy.x), "f"(sy.y) : "memory");
            asm volatile("red.global.add.v2.f32 [%0], {%1, %2};"
                         :: "l"(out + (size_t)c.z * 2), "f"(sz.x), "f"(sz.y) : "memory");
            asm volatile("red.global.add.v2.f32 [%0], {%1, %2};"
                         :: "l"(out + (size_t)c.w * 2), "f"(sw.x), "f"(sw.y) : "memory");
        }
        if (blockIdx.x == 0 && tid < (n_edges & 3)) {
            int e = (n4 << 2) + tid;
            int r1 = row[e], c1 = col[e];
            float2 sv = __ldg(reinterpret_cast<const float2*>(g_s) + r1);
            asm volatile("red.global.add.v2.f32 [%0], {%1, %2};"
                         :: "l"(out + (size_t)c1 * 2), "f"(sv.x), "f"(sv.y) : "memory");
        }
    }

    grid_barrier(3u * G);

    // ============ Phase D: out = out*dinv + c; re-zero g_deg ==============
    {
        float c0 = g_c[0], c1 = g_c[1];
        int n2 = (n_nodes + 1) >> 1;
        int stride = G * blockDim.x;
        for (int t = blockIdx.x * blockDim.x + tid; t < n2; t += stride) {
            int i = t * 2;
            if (i + 1 < n_nodes) {
                float4 a = *reinterpret_cast<float4*>(out + i * 2);
                float2 d = *reinterpret_cast<float2*>(g_dinv + i);
                a.x = a.x * d.x + c0;  a.y = a.y * d.x + c1;
                a.z = a.z * d.y + c0;  a.w = a.w * d.y + c1;
                *reinterpret_cast<float4*>(out + i * 2) = a;
                *reinterpret_cast<int2*>(g_deg + i) = make_int2(0, 0);
            } else {
                float di = g_dinv[i];
                float2 a = reinterpret_cast<float2*>(out)[i];
                a.x = a.x * di + c0;
                a.y = a.y * di + c1;
                reinterpret_cast<float2*>(out)[i] = a;
                g_deg[i] = 0;
            }
        }
    }

    // ---- arrive-only 4th step: last arriver resets the barrier counter ----
    __syncthreads();
    if (tid == 0) {
        __threadfence();
        unsigned v = atomicAdd(&g_bar, 1u);
        if (v == 4u * G - 1u) g_bar = 0;   // all blocks done; safe to reset
    }
}

// ---------------------------------------------------------------------------
extern "C" void kernel_launch(void* const* d_in, const int* in_sizes, int n_in,
                              void* d_out, int out_size) {
    const float* x  = (const float*)d_in[0];
    const int*   ei = (const int*)d_in[1];   // [2, E]
    const float* W1 = (const float*)d_in[2];
    const float* b1 = (const float*)d_in[3];
    const float* W2 = (const float*)d_in[4];
    const float* b2 = (const float*)d_in[5];
    float* out = (float*)d_out;

    const int n_edges = in_sizes[1] / 2;
    const int n_nodes = out_size / OUT_CH;
    const int* row = ei;             // source nodes
    const int* col = ei + n_edges;   // target nodes

    int dev = 0, sms = 148;
    cudaGetDevice(&dev);
    cudaDeviceGetAttribute(&sms, cudaDevAttrMultiProcessorCount, dev);
    const int grid = 2 * sms;                 // all resident (launch_bounds 256,2)
    const int deg_blocks = grid / 5;          // ~20% of blocks on degree atomics

    gcn_kernel<<<grid, 256>>>(x, row, col, W1, b1, W2, b2, out,
                              n_edges, n_nodes, deg_blocks);
}